// round 2
// baseline (speedup 1.0000x reference)
#include <cuda_runtime.h>

#define HIDDEN   256
#define LATENT   128
#define VOCAB    32000
#define MAX_LEN  64
#define MAX_STEPS 128
#define N_NODES  511

// ------------------- device scratch (no allocations allowed) -------------------
__device__ __align__(16) float g_emb[N_NODES * HIDDEN];
__device__ __align__(16) float g_h[N_NODES * HIDDEN];
__device__ __align__(16) float g_WparT[768 * HIDDEN];       // [k][j]
__device__ __align__(16) float g_W1T[LATENT * HIDDEN];      // [k][j]  j<256,k<128
__device__ __align__(16) float g_W2T[HIDDEN * HIDDEN];      // [k][j] rows 1..256 of W2
__device__ __align__(16) float g_WpCT[HIDDEN * HIDDEN];     // [m][j]: C[j][m]=sum_k WpTail[j][k]*W2[1+k][m]
__device__ __align__(16) float g_bpC[HIDDEN];
__device__ __align__(16) float g_z[LATENT];
__device__ __align__(16) float g_H[MAX_STEPS * HIDDEN];     // hmid per active step
__device__ __align__(16) float g_CO[MAX_STEPS * HIDDEN];    // co[1:] per active step
__device__ int g_leafRows[MAX_STEPS];
__device__ int g_parRows[MAX_STEPS];
__device__ int g_nLeaf;
__device__ int g_nPar;
__device__ int g_nOut;

// ------------------- prep: transposes -------------------
__global__ void prep_transpose(const float* __restrict__ Wpar,
                               const float* __restrict__ W1,
                               const float* __restrict__ W2) {
    int i = blockIdx.x * blockDim.x + threadIdx.x;
    int stride = gridDim.x * blockDim.x;
    const int NPAR = 768 * 256;          // 196608
    const int NW1  = 128 * 256;          // 32768
    const int NW2  = 256 * 256;          // 65536
    for (; i < NPAR + NW1 + NW2; i += stride) {
        if (i < NPAR) {
            int k = i >> 8, j = i & 255;
            g_WparT[i] = Wpar[j * 768 + k];
        } else if (i < NPAR + NW1) {
            int o = i - NPAR;
            int k = o >> 8, j = o & 255;
            g_W1T[o] = W1[j * LATENT + k];
        } else {
            int o = i - NPAR - NW1;
            int k = o >> 8, j = o & 255;
            g_W2T[o] = W2[(1 + j) * HIDDEN + k];
        }
    }
}

// ------------------- prep: fold Wp tail through W2[1:] -------------------
// C[j][m] = sum_k Wp[V+j][k] * W2[1+k][m];  bpC[j] = sum_k Wp[V+j][k]*b2[1+k] + bp[V+j]
__global__ void prep_wpc(const float* __restrict__ Wp, const float* __restrict__ W2,
                         const float* __restrict__ b2, const float* __restrict__ bp) {
    __shared__ float wrow[256];
    __shared__ float red[8];
    int j = blockIdx.x, t = threadIdx.x;
    wrow[t] = Wp[(long)(VOCAB + j) * HIDDEN + t];
    __syncthreads();
    float a0 = 0.f, a1 = 0.f, a2 = 0.f, a3 = 0.f;
    #pragma unroll 4
    for (int k = 0; k < 256; k += 4) {
        a0 += wrow[k + 0] * W2[(1 + k) * 256 + t];
        a1 += wrow[k + 1] * W2[(2 + k) * 256 + t];
        a2 += wrow[k + 2] * W2[(3 + k) * 256 + t];
        a3 += wrow[k + 3] * W2[(4 + k) * 256 + t];
    }
    g_WpCT[t * 256 + j] = (a0 + a1) + (a2 + a3);
    float p = wrow[t] * b2[1 + t];
    #pragma unroll
    for (int o = 16; o; o >>= 1) p += __shfl_xor_sync(0xFFFFFFFFu, p, o);
    if ((t & 31) == 0) red[t >> 5] = p;
    __syncthreads();
    if (t == 0) {
        float s = bp[VOCAB + j];
        #pragma unroll
        for (int w = 0; w < 8; w++) s += red[w];
        g_bpC[j] = s;
    }
}

// ------------------- encoder: gather embeddings, init leaves -------------------
__global__ void gather_k(const float* __restrict__ embed, const int* __restrict__ values) {
    int i = blockIdx.x, t = threadIdx.x;
    float v = embed[(long)values[i] * HIDDEN + t];
    g_emb[i * HIDDEN + t] = v;
    if (i >= 255) g_h[i * HIDDEN + t] = v;   // leaves
}

// ------------------- encoder: one tree level, 2 nodes per block -------------------
__global__ void __launch_bounds__(256) enc_level(const float* __restrict__ bpar,
                                                 int first, int count) {
    __shared__ float cat[2][768];
    int t = threadIdx.x;
    int n0 = first + blockIdx.x * 2;
    int nn = (n0 + 1 < first + count) ? 2 : 1;
    for (int ln = 0; ln < nn; ln++) {
        int n = n0 + ln;
        cat[ln][t]       = g_emb[n * HIDDEN + t];
        cat[ln][256 + t] = g_h[(2 * n + 1) * HIDDEN + t];
        cat[ln][512 + t] = g_h[(2 * n + 2) * HIDDEN + t];
    }
    __syncthreads();
    bool two = (nn == 2);
    float a0 = 0.f, a1 = 0.f, a2 = 0.f, a3 = 0.f;
    float c0 = 0.f, c1 = 0.f, c2 = 0.f, c3 = 0.f;
    #pragma unroll 4
    for (int k = 0; k < 768; k += 4) {
        float w0 = g_WparT[(k + 0) * 256 + t];
        float w1 = g_WparT[(k + 1) * 256 + t];
        float w2 = g_WparT[(k + 2) * 256 + t];
        float w3 = g_WparT[(k + 3) * 256 + t];
        a0 += w0 * cat[0][k + 0];  a1 += w1 * cat[0][k + 1];
        a2 += w2 * cat[0][k + 2];  a3 += w3 * cat[0][k + 3];
        if (two) {
            c0 += w0 * cat[1][k + 0];  c1 += w1 * cat[1][k + 1];
            c2 += w2 * cat[1][k + 2];  c3 += w3 * cat[1][k + 3];
        }
    }
    float bb = bpar[t];
    g_h[n0 * HIDDEN + t] = (a0 + a1) + (a2 + a3) + bb;
    if (two) g_h[(n0 + 1) * HIDDEN + t] = (c0 + c1) + (c2 + c3) + bb;
}

// ------------------- latent head -------------------
__global__ void latent_k(const float* __restrict__ Wmu, const float* __restrict__ bmu,
                         const float* __restrict__ Wlv, const float* __restrict__ blv,
                         const float* __restrict__ eps, float* __restrict__ out) {
    __shared__ float root[256];
    __shared__ float mu_s[128];
    __shared__ float lv_s[128];
    int t = threadIdx.x;
    root[t] = g_h[t];
    __syncthreads();
    if (t < 128) {
        float a = bmu[t];
        #pragma unroll 4
        for (int k = 0; k < 256; k++) a += Wmu[t * 256 + k] * root[k];
        mu_s[t] = a;
        out[(long)MAX_STEPS * VOCAB + t] = a;
    } else {
        int j = t - 128;
        float a = blv[j];
        #pragma unroll 4
        for (int k = 0; k < 256; k++) a += Wlv[j * 256 + k] * root[k];
        lv_s[j] = a;
        out[(long)MAX_STEPS * VOCAB + 128 + j] = a;
    }
    __syncthreads();
    if (t < 128) g_z[t] = mu_s[t] + eps[t] * expf(0.5f * lv_s[t]);
}

// ------------------- sequential decoder control (single CTA) -------------------
__global__ void __launch_bounds__(256) dec_control(const float* __restrict__ b1,
                                                   const float* __restrict__ W2,
                                                   const float* __restrict__ b2) {
    __shared__ float stack[MAX_LEN][LATENT];
    __shared__ float hmid[256];
    __shared__ float red[8];
    int t = threadIdx.x;
    if (t < 128) stack[0][t] = g_z[t];
    float b1v  = b1[t];
    float w2r0 = W2[t];        // row 0 of W2
    float b20  = b2[0];
    float bpc  = g_bpC[t];
    __syncthreads();

    int sp = 1, op = 0, nl = 0, np = 0;
    for (int step = 0; step < MAX_STEPS && sp > 0; step++) {
        int idx = sp - 1;
        const float* xr = stack[idx];
        // phase 1: hmid = leaky_relu(W1 @ x + b1)
        float a0 = 0.f, a1 = 0.f, a2 = 0.f, a3 = 0.f;
        #pragma unroll 4
        for (int k = 0; k < 128; k += 4) {
            a0 += g_W1T[(k + 0) * 256 + t] * xr[k + 0];
            a1 += g_W1T[(k + 1) * 256 + t] * xr[k + 1];
            a2 += g_W1T[(k + 2) * 256 + t] * xr[k + 2];
            a3 += g_W1T[(k + 3) * 256 + t] * xr[k + 3];
        }
        float hm = (a0 + a1) + (a2 + a3) + b1v;
        hm = hm > 0.f ? hm : 0.2f * hm;
        hmid[t] = hm;
        g_H[op * 256 + t] = hm;                 // record for deferred GEMMs
        // co[0] reduction
        float p = w2r0 * hm;
        #pragma unroll
        for (int o = 16; o; o >>= 1) p += __shfl_xor_sync(0xFFFFFFFFu, p, o);
        if ((t & 31) == 0) red[t >> 5] = p;
        __syncthreads();
        float co0 = b20 + ((red[0] + red[1]) + (red[2] + red[3]))
                        + ((red[4] + red[5]) + (red[6] + red[7]));
        bool parent = (co0 > 0.f) && (idx <= MAX_LEN - 2);
        if (parent) {
            // llrl = hmid @ C^T + bpC  (folded through W2[1:])
            float d0 = 0.f, d1 = 0.f, d2 = 0.f, d3 = 0.f;
            #pragma unroll 4
            for (int m = 0; m < 256; m += 4) {
                d0 += g_WpCT[(m + 0) * 256 + t] * hmid[m + 0];
                d1 += g_WpCT[(m + 1) * 256 + t] * hmid[m + 1];
                d2 += g_WpCT[(m + 2) * 256 + t] * hmid[m + 2];
                d3 += g_WpCT[(m + 3) * 256 + t] * hmid[m + 3];
            }
            float d = (d0 + d1) + (d2 + d3) + bpc;
            if (t < 128) stack[idx][t] = d;           // ll
            else         stack[idx + 1][t - 128] = d; // rl
            if (t == 0) g_parRows[np] = op;
            np++; sp++;
        } else {
            if (t == 0) g_leafRows[nl] = op;
            nl++; sp--;
        }
        op++;
        __syncthreads();
    }
    if (t == 0) { g_nLeaf = nl; g_nPar = np; g_nOut = op; }
}

// ------------------- batched co[1:] = H @ W2[1:]^T + b2[1:] -------------------
__global__ void co1_k(const float* __restrict__ b2) {
    __shared__ float hr[256];
    int r = blockIdx.x, t = threadIdx.x;
    if (r >= g_nOut) return;
    hr[t] = g_H[r * 256 + t];
    __syncthreads();
    float a0 = 0.f, a1 = 0.f, a2 = 0.f, a3 = 0.f;
    #pragma unroll 4
    for (int k = 0; k < 256; k += 4) {
        a0 += g_W2T[(k + 0) * 256 + t] * hr[k + 0];
        a1 += g_W2T[(k + 1) * 256 + t] * hr[k + 1];
        a2 += g_W2T[(k + 2) * 256 + t] * hr[k + 2];
        a3 += g_W2T[(k + 3) * 256 + t] * hr[k + 3];
    }
    g_CO[r * 256 + t] = (a0 + a1) + (a2 + a3) + b2[1 + t];
}

// ------------------- zero rows >= nOut -------------------
__global__ void zero_rows(float* __restrict__ out) {
    int r = blockIdx.x;
    if (r < g_nOut) return;
    float4* o = reinterpret_cast<float4*>(out + (long)r * VOCAB);
    float4 z = make_float4(0.f, 0.f, 0.f, 0.f);
    for (int i = threadIdx.x; i < VOCAB / 4; i += 256) o[i] = z;
}

// ------------------- deferred value GEMM: out[rows] = CO @ W^T + bias -------------------
// which = 0 -> leaf list, 1 -> parent list. grid.x = 250 vocab tiles of 128.
__global__ void __launch_bounds__(256) value_gemm(const float* __restrict__ W,
                                                  const float* __restrict__ bias,
                                                  int which, float* __restrict__ out) {
    __shared__ float Cs[64 * 140];   // [k][m], pad 140 -> 4-way conflicts max
    __shared__ int rs[128];
    int t = threadIdx.x;
    int cnt = which ? g_nPar : g_nLeaf;
    if (cnt == 0) return;
    const int* rows = which ? g_parRows : g_leafRows;
    if (t < 128) rs[t] = (t < cnt) ? rows[t] : 0;

    int vi = t & 31, mi = t >> 5;      // 32 v-groups x 8 m-groups
    int v0 = blockIdx.x * 128;
    float acc[16][4];
    #pragma unroll
    for (int i = 0; i < 16; i++)
        #pragma unroll
        for (int c = 0; c < 4; c++) acc[i][c] = 0.f;

    const float* Wbase = W + (long)(v0 + vi * 4) * 256;

    for (int kc = 0; kc < 256; kc += 64) {
        __syncthreads();
        // stage CO tile [64 k][128 m], coalesced gather, zero-pad m >= cnt
        for (int idx = t; idx < 64 * 128; idx += 256) {
            int k = idx & 63, m = idx >> 6;
            float val = (m < cnt) ? g_CO[rs[m] * 256 + kc + k] : 0.f;
            Cs[k * 140 + m] = val;
        }
        __syncthreads();
        #pragma unroll 2
        for (int k4 = 0; k4 < 64; k4 += 4) {
            float4 b0 = *reinterpret_cast<const float4*>(Wbase + 0 * 256 + kc + k4);
            float4 b1 = *reinterpret_cast<const float4*>(Wbase + 1 * 256 + kc + k4);
            float4 b2v = *reinterpret_cast<const float4*>(Wbase + 2 * 256 + kc + k4);
            float4 b3 = *reinterpret_cast<const float4*>(Wbase + 3 * 256 + kc + k4);
            float bw0[4] = {b0.x, b0.y, b0.z, b0.w};
            float bw1[4] = {b1.x, b1.y, b1.z, b1.w};
            float bw2[4] = {b2v.x, b2v.y, b2v.z, b2v.w};
            float bw3[4] = {b3.x, b3.y, b3.z, b3.w};
            #pragma unroll
            for (int kk = 0; kk < 4; kk++) {
                const float* arow = &Cs[(k4 + kk) * 140 + mi * 16];
                float4 A0 = *reinterpret_cast<const float4*>(arow + 0);
                float4 A1 = *reinterpret_cast<const float4*>(arow + 4);
                float4 A2 = *reinterpret_cast<const float4*>(arow + 8);
                float4 A3 = *reinterpret_cast<const float4*>(arow + 12);
                float av[16] = {A0.x, A0.y, A0.z, A0.w, A1.x, A1.y, A1.z, A1.w,
                                A2.x, A2.y, A2.z, A2.w, A3.x, A3.y, A3.z, A3.w};
                float c0 = bw0[kk], c1 = bw1[kk], c2 = bw2[kk], c3 = bw3[kk];
                #pragma unroll
                for (int i = 0; i < 16; i++) {
                    acc[i][0] += av[i] * c0;
                    acc[i][1] += av[i] * c1;
                    acc[i][2] += av[i] * c2;
                    acc[i][3] += av[i] * c3;
                }
            }
        }
    }
    float4 bb = *reinterpret_cast<const float4*>(bias + v0 + vi * 4);
    #pragma unroll
    for (int i = 0; i < 16; i++) {
        int m = mi * 16 + i;
        if (m < cnt) {
            long ro = (long)rs[m] * VOCAB + v0 + vi * 4;
            *reinterpret_cast<float4*>(out + ro) =
                make_float4(acc[i][0] + bb.x, acc[i][1] + bb.y,
                            acc[i][2] + bb.z, acc[i][3] + bb.w);
        }
    }
}

// ------------------- launch -------------------
extern "C" void kernel_launch(void* const* d_in, const int* in_sizes, int n_in,
                              void* d_out, int out_size) {
    const float* embed = (const float*)d_in[0];
    const float* Wpar  = (const float*)d_in[1];
    const float* bpar  = (const float*)d_in[2];
    const float* Wmu   = (const float*)d_in[3];
    const float* bmu   = (const float*)d_in[4];
    const float* Wlv   = (const float*)d_in[5];
    const float* blv   = (const float*)d_in[6];
    const float* W1    = (const float*)d_in[7];
    const float* b1    = (const float*)d_in[8];
    const float* W2    = (const float*)d_in[9];
    const float* b2    = (const float*)d_in[10];
    const float* Wl    = (const float*)d_in[11];
    const float* bl    = (const float*)d_in[12];
    const float* Wp    = (const float*)d_in[13];
    const float* bp    = (const float*)d_in[14];
    const float* eps   = (const float*)d_in[15];
    const int*   values= (const int*)d_in[16];
    float* out = (float*)d_out;

    prep_transpose<<<288, 1024>>>(Wpar, W1, W2);
    prep_wpc<<<256, 256>>>(Wp, W2, b2, bp);
    gather_k<<<N_NODES, 256>>>(embed, values);
    for (int d = 7; d >= 0; d--) {
        int first = (1 << d) - 1;
        int count = 1 << d;
        int blocks = (count + 1) / 2;
        enc_level<<<blocks, 256>>>(bpar, first, count);
    }
    latent_k<<<1, 256>>>(Wmu, bmu, Wlv, blv, eps, out);
    dec_control<<<1, 256>>>(b1, W2, b2);
    co1_k<<<MAX_STEPS, 256>>>(b2);
    zero_rows<<<MAX_STEPS, 256>>>(out);
    value_gemm<<<VOCAB / 128, 256>>>(Wl, bl, 0, out);
    value_gemm<<<VOCAB / 128, 256>>>(Wp, bp, 1, out);
}

// round 3
// speedup vs baseline: 1.6029x; 1.6029x over previous
#include <cuda_runtime.h>
#include <cstdint>

#define HIDDEN   256
#define LATENT   128
#define VOCAB    32000
#define MAX_LEN  64
#define MAX_STEPS 128
#define N_NODES  511

// ------------------- device scratch -------------------
__device__ __align__(16) float g_h[N_NODES * HIDDEN];
__device__ __align__(16) float g_W2T[HIDDEN * HIDDEN];   // [k][j], rows 1..256 of W2
__device__ __align__(16) float g_WpCT[HIDDEN * HIDDEN];  // [m][j]
__device__ __align__(16) float g_bpC[HIDDEN];
__device__ __align__(16) float g_z[LATENT];
__device__ __align__(16) float g_H[MAX_STEPS * HIDDEN];
__device__ __align__(16) float g_CO[MAX_STEPS * HIDDEN];
__device__ int g_leafRows[MAX_STEPS];
__device__ int g_parRows[MAX_STEPS];
__device__ int g_nLeaf;
__device__ int g_nPar;
__device__ int g_nOut;

// ------------------- PTX helpers -------------------
__device__ __forceinline__ uint32_t s2u(const void* p) {
    uint32_t a;
    asm("{ .reg .u64 t; cvta.to.shared.u64 t, %1; cvt.u32.u64 %0, t; }" : "=r"(a) : "l"(p));
    return a;
}
__device__ __forceinline__ uint32_t ctarank() {
    uint32_t r; asm("mov.u32 %0, %%cluster_ctarank;" : "=r"(r)); return r;
}
__device__ __forceinline__ void st_cluster_f(uint32_t saddr, uint32_t rank, float v) {
    uint32_t ra;
    asm volatile("mapa.shared::cluster.u32 %0, %1, %2;" : "=r"(ra) : "r"(saddr), "r"(rank));
    asm volatile("st.shared::cluster.b32 [%0], %1;" :: "r"(ra), "r"(__float_as_uint(v)) : "memory");
}
#define CLUSTER_SYNC() do { \
    asm volatile("barrier.cluster.arrive.aligned;" ::: "memory"); \
    asm volatile("barrier.cluster.wait.aligned;" ::: "memory"); \
} while (0)

// ------------------- prep: W2 tail transpose -------------------
__global__ void prep_w2t(const float* __restrict__ W2) {
    int i = blockIdx.x * blockDim.x + threadIdx.x;   // 65536
    int j = i >> 8, k = i & 255;                     // read coalesced over k
    g_W2T[k * 256 + j] = W2[(1 + j) * 256 + k];
}

// ------------------- prep: fold Wp tail through W2[1:] -------------------
__global__ void prep_wpc(const float* __restrict__ Wp, const float* __restrict__ W2,
                         const float* __restrict__ b2, const float* __restrict__ bp) {
    __shared__ float wrow[256];
    __shared__ float red[8];
    int j = blockIdx.x, t = threadIdx.x;
    wrow[t] = Wp[(long)(VOCAB + j) * HIDDEN + t];
    __syncthreads();
    float a0 = 0.f, a1 = 0.f, a2 = 0.f, a3 = 0.f;
    #pragma unroll 4
    for (int k = 0; k < 256; k += 4) {
        a0 += wrow[k + 0] * W2[(1 + k) * 256 + t];
        a1 += wrow[k + 1] * W2[(2 + k) * 256 + t];
        a2 += wrow[k + 2] * W2[(3 + k) * 256 + t];
        a3 += wrow[k + 3] * W2[(4 + k) * 256 + t];
    }
    g_WpCT[t * 256 + j] = (a0 + a1) + (a2 + a3);
    float p = wrow[t] * b2[1 + t];
    #pragma unroll
    for (int o = 16; o; o >>= 1) p += __shfl_xor_sync(0xFFFFFFFFu, p, o);
    if ((t & 31) == 0) red[t >> 5] = p;
    __syncthreads();
    if (t == 0) {
        float s = bp[VOCAB + j];
        #pragma unroll
        for (int w = 0; w < 8; w++) s += red[w];
        g_bpC[j] = s;
    }
}

// ------------------- encoder level: warp-per-2-outputs, lanes over k -------------------
__global__ void __launch_bounds__(256) enc_level(
    const float* __restrict__ embed, const int* __restrict__ values,
    const float* __restrict__ Wpar, const float* __restrict__ bpar,
    int first, int count, int leafkids)
{
    __shared__ __align__(16) float cat[2][768];
    int t = threadIdx.x;
    int n0 = first + blockIdx.x * 2;
    bool two = (n0 + 1 < first + count);
    #pragma unroll
    for (int ln = 0; ln < 2; ln++) {
        if (ln == 1 && !two) {
            cat[1][t] = 0.f; cat[1][256 + t] = 0.f; cat[1][512 + t] = 0.f;
        } else {
            int n = n0 + ln;
            cat[ln][t] = embed[(long)values[n] * 256 + t];
            int li = 2 * n + 1, ri = 2 * n + 2;
            if (leafkids) {
                cat[ln][256 + t] = embed[(long)values[li] * 256 + t];
                cat[ln][512 + t] = embed[(long)values[ri] * 256 + t];
            } else {
                cat[ln][256 + t] = g_h[li * 256 + t];
                cat[ln][512 + t] = g_h[ri * 256 + t];
            }
        }
    }
    __syncthreads();
    int w = t >> 5, l = t & 31;
    const float4* W4 = reinterpret_cast<const float4*>(Wpar);
    const float4* c0 = reinterpret_cast<const float4*>(cat[0]);
    const float4* c1 = reinterpret_cast<const float4*>(cat[1]);
    for (int rr = 0; rr < 32; rr += 2) {
        int j0 = w * 32 + rr;
        float a0 = 0.f, a1 = 0.f, b0 = 0.f, b1 = 0.f;
        #pragma unroll
        for (int it = 0; it < 6; it++) {
            int ki = it * 32 + l;
            float4 w0 = W4[(long)j0 * 192 + ki];
            float4 w1 = W4[(long)(j0 + 1) * 192 + ki];
            float4 v0 = c0[ki];
            float4 v1 = c1[ki];
            a0 += w0.x * v0.x + w0.y * v0.y + w0.z * v0.z + w0.w * v0.w;
            a1 += w1.x * v0.x + w1.y * v0.y + w1.z * v0.z + w1.w * v0.w;
            b0 += w0.x * v1.x + w0.y * v1.y + w0.z * v1.z + w0.w * v1.w;
            b1 += w1.x * v1.x + w1.y * v1.y + w1.z * v1.z + w1.w * v1.w;
        }
        #pragma unroll
        for (int o = 16; o; o >>= 1) {
            a0 += __shfl_xor_sync(0xFFFFFFFFu, a0, o);
            a1 += __shfl_xor_sync(0xFFFFFFFFu, a1, o);
            b0 += __shfl_xor_sync(0xFFFFFFFFu, b0, o);
            b1 += __shfl_xor_sync(0xFFFFFFFFu, b1, o);
        }
        if (l == 0) {
            float bb0 = bpar[j0], bb1 = bpar[j0 + 1];
            g_h[n0 * 256 + j0]     = a0 + bb0;
            g_h[n0 * 256 + j0 + 1] = a1 + bb1;
            if (two) {
                g_h[(n0 + 1) * 256 + j0]     = b0 + bb0;
                g_h[(n0 + 1) * 256 + j0 + 1] = b1 + bb1;
            }
        }
    }
}

// ------------------- latent head -------------------
__global__ void latent_k(const float* __restrict__ Wmu, const float* __restrict__ bmu,
                         const float* __restrict__ Wlv, const float* __restrict__ blv,
                         const float* __restrict__ eps, float* __restrict__ out) {
    __shared__ float root[256];
    __shared__ float mu_s[128];
    __shared__ float lv_s[128];
    int t = threadIdx.x;
    root[t] = g_h[t];
    __syncthreads();
    if (t < 128) {
        float a = bmu[t];
        #pragma unroll 4
        for (int k = 0; k < 256; k++) a += Wmu[t * 256 + k] * root[k];
        mu_s[t] = a;
        out[(long)MAX_STEPS * VOCAB + t] = a;
    } else {
        int j = t - 128;
        float a = blv[j];
        #pragma unroll 4
        for (int k = 0; k < 256; k++) a += Wlv[j * 256 + k] * root[k];
        lv_s[j] = a;
        out[(long)MAX_STEPS * VOCAB + 128 + j] = a;
    }
    __syncthreads();
    if (t < 128) g_z[t] = mu_s[t] + eps[t] * expf(0.5f * lv_s[t]);
}

// ------------------- decoder control: 8-CTA cluster, weights in SMEM -------------------
// smem floats: W1s 4096 | WpCs 8192 | stack 8192 | hmid 512 (x2 buf) | llrl 256 |
//              w2r0 256 | red 256 | cored 8
#define DEC_SMEM_FLOATS (4096 + 8192 + 8192 + 512 + 256 + 256 + 256 + 8)
#define DEC_SMEM_BYTES  (DEC_SMEM_FLOATS * 4)

__global__ void __cluster_dims__(8, 1, 1) __launch_bounds__(256, 1)
dec_cluster(const float* __restrict__ W1, const float* __restrict__ b1,
            const float* __restrict__ W2, const float* __restrict__ b2)
{
    extern __shared__ float S[];
    float* W1s   = S;                 // [k 128][j' 32]
    float* WpCs  = W1s + 4096;        // [m 256][j' 32]
    float* stack = WpCs + 8192;       // [64][128]
    float* hmid  = stack + 8192;      // [2][256]
    float* llrl  = hmid + 512;        // [256]
    float* w2r0  = llrl + 256;        // [256]
    float* red   = w2r0 + 256;        // [256]
    float* cored = red + 256;         // [8]

    int t = threadIdx.x;
    uint32_t rank = ctarank();
    int rowbase = (int)rank * 32;
    int j2 = t & 31, kg = t >> 5;

    // load W1 slice, coalesced over k
    for (int i = t; i < 4096; i += 256) {
        int jp = i >> 7, k = i & 127;
        W1s[k * 32 + jp] = W1[(rowbase + jp) * 128 + k];
    }
    // load WpC slice
    for (int i = t; i < 8192; i += 256) {
        int m = i >> 5, jp = i & 31;
        WpCs[i] = g_WpCT[m * 256 + rowbase + jp];
    }
    for (int i = t; i < 8192; i += 256) stack[i] = 0.f;
    w2r0[t] = W2[t];
    __syncthreads();
    if (t < 128) stack[t] = g_z[t];
    float b1v  = (t < 32) ? b1[rowbase + t] : 0.f;
    float bpcv = (t < 32) ? g_bpC[rowbase + t] : 0.f;
    float b20  = b2[0];
    __syncthreads();
    CLUSTER_SYNC();

    int sp = 1, op = 0, nl = 0, np = 0;
    for (int step = 0; step < MAX_STEPS && sp > 0; step++) {
        int idx = sp - 1;
        float* hb = hmid + (step & 1) * 256;
        const float* x = stack + idx * 128;

        // phase 1: hmid slice partials (8 k-groups x 32 outputs)
        float acc = 0.f;
        int k0 = kg * 16;
        #pragma unroll
        for (int kk = 0; kk < 16; kk++)
            acc += W1s[(k0 + kk) * 32 + j2] * x[k0 + kk];
        red[kg * 32 + j2] = acc;
        __syncthreads();
        if (t < 32) {
            float v = b1v;
            #pragma unroll
            for (int g = 0; g < 8; g++) v += red[g * 32 + t];
            v = v > 0.f ? v : 0.2f * v;
            uint32_t sa = s2u(&hb[rowbase + t]);
            #pragma unroll
            for (int r = 0; r < 8; r++) st_cluster_f(sa, (uint32_t)r, v);
        }
        CLUSTER_SYNC();   // sync 1: full hmid visible everywhere

        if (rank == 0) g_H[op * 256 + t] = hb[t];

        // co[0] (redundant on every CTA, deterministic)
        float p = w2r0[t] * hb[t];
        #pragma unroll
        for (int o = 16; o; o >>= 1) p += __shfl_xor_sync(0xFFFFFFFFu, p, o);
        if (j2 == 0) cored[kg] = p;
        __syncthreads();
        float co0 = b20;
        #pragma unroll
        for (int g = 0; g < 8; g++) co0 += cored[g];
        bool parent = (co0 > 0.f) && (idx <= MAX_LEN - 2);

        if (parent) {
            // llrl slice: 256 -> 32 per CTA (folded WpC)
            float d = 0.f;
            int m0 = kg * 32;
            #pragma unroll
            for (int mm = 0; mm < 32; mm++)
                d += WpCs[(m0 + mm) * 32 + j2] * hb[m0 + mm];
            red[kg * 32 + j2] = d;
            __syncthreads();
            if (t < 32) {
                float v = bpcv;
                #pragma unroll
                for (int g = 0; g < 8; g++) v += red[g * 32 + t];
                uint32_t sa = s2u(&llrl[rowbase + t]);
                #pragma unroll
                for (int r = 0; r < 8; r++) st_cluster_f(sa, (uint32_t)r, v);
            }
            CLUSTER_SYNC();   // sync 2: full llrl visible
            if (t < 128) stack[idx * 128 + t] = llrl[t];
            else         stack[(idx + 1) * 128 + (t - 128)] = llrl[t];
            if (rank == 0 && t == 0) g_parRows[np] = op;
            np++; sp++;
        } else {
            if (rank == 0 && t == 0) g_leafRows[nl] = op;
            nl++; sp--;
        }
        op++;
        __syncthreads();
    }
    if (rank == 0 && t == 0) { g_nLeaf = nl; g_nPar = np; g_nOut = op; }
}

// ------------------- batched co[1:] = H @ W2[1:]^T + b2[1:] -------------------
__global__ void co1_k(const float* __restrict__ b2) {
    __shared__ float hr[256];
    int r = blockIdx.x, t = threadIdx.x;
    if (r >= g_nOut) return;
    hr[t] = g_H[r * 256 + t];
    __syncthreads();
    float a0 = 0.f, a1 = 0.f, a2 = 0.f, a3 = 0.f;
    #pragma unroll 4
    for (int k = 0; k < 256; k += 4) {
        a0 += g_W2T[(k + 0) * 256 + t] * hr[k + 0];
        a1 += g_W2T[(k + 1) * 256 + t] * hr[k + 1];
        a2 += g_W2T[(k + 2) * 256 + t] * hr[k + 2];
        a3 += g_W2T[(k + 3) * 256 + t] * hr[k + 3];
    }
    g_CO[r * 256 + t] = (a0 + a1) + (a2 + a3) + b2[1 + t];
}

// ------------------- zero rows >= nOut -------------------
__global__ void zero_rows(float* __restrict__ out) {
    int r = blockIdx.x;
    if (r < g_nOut) return;
    float4* o = reinterpret_cast<float4*>(out + (long)r * VOCAB);
    float4 z = make_float4(0.f, 0.f, 0.f, 0.f);
    for (int i = threadIdx.x; i < VOCAB / 4; i += 256) o[i] = z;
}

// ------------------- deferred value GEMM (leaf + parent via blockIdx.y) -------------------
__global__ void __launch_bounds__(256) value_gemm(const float* __restrict__ Wl,
                                                  const float* __restrict__ bl,
                                                  const float* __restrict__ Wp,
                                                  const float* __restrict__ bp,
                                                  float* __restrict__ out) {
    __shared__ float Cs[64 * 140];
    __shared__ int rs[128];
    int t = threadIdx.x;
    int which = blockIdx.y;
    int cnt = which ? g_nPar : g_nLeaf;
    if (cnt == 0) return;
    const float* W    = which ? Wp : Wl;
    const float* bias = which ? bp : bl;
    const int*  rows  = which ? g_parRows : g_leafRows;
    if (t < 128) rs[t] = (t < cnt) ? rows[t] : 0;

    int mlim = (cnt + 15) & ~15;
    int vi = t & 31, mi = t >> 5;
    bool active = (mi * 16) < cnt;
    int v0 = blockIdx.x * 128;
    float acc[16][4];
    #pragma unroll
    for (int i = 0; i < 16; i++)
        #pragma unroll
        for (int c = 0; c < 4; c++) acc[i][c] = 0.f;

    const float* Wbase = W + (long)(v0 + vi * 4) * 256;

    for (int kc = 0; kc < 256; kc += 64) {
        __syncthreads();
        for (int idx = t; idx < 64 * mlim; idx += 256) {
            int k = idx & 63, m = idx >> 6;
            Cs[k * 140 + m] = (m < cnt) ? g_CO[rs[m] * 256 + kc + k] : 0.f;
        }
        __syncthreads();
        if (active) {
            #pragma unroll 2
            for (int k4 = 0; k4 < 64; k4 += 4) {
                float4 r0 = *reinterpret_cast<const float4*>(Wbase + 0 * 256 + kc + k4);
                float4 r1 = *reinterpret_cast<const float4*>(Wbase + 1 * 256 + kc + k4);
                float4 r2 = *reinterpret_cast<const float4*>(Wbase + 2 * 256 + kc + k4);
                float4 r3 = *reinterpret_cast<const float4*>(Wbase + 3 * 256 + kc + k4);
                float bw0[4] = {r0.x, r0.y, r0.z, r0.w};
                float bw1[4] = {r1.x, r1.y, r1.z, r1.w};
                float bw2[4] = {r2.x, r2.y, r2.z, r2.w};
                float bw3[4] = {r3.x, r3.y, r3.z, r3.w};
                #pragma unroll
                for (int kk = 0; kk < 4; kk++) {
                    const float* arow = &Cs[(k4 + kk) * 140 + mi * 16];
                    float4 A0 = *reinterpret_cast<const float4*>(arow + 0);
                    float4 A1 = *reinterpret_cast<const float4*>(arow + 4);
                    float4 A2 = *reinterpret_cast<const float4*>(arow + 8);
                    float4 A3 = *reinterpret_cast<const float4*>(arow + 12);
                    float av[16] = {A0.x, A0.y, A0.z, A0.w, A1.x, A1.y, A1.z, A1.w,
                                    A2.x, A2.y, A2.z, A2.w, A3.x, A3.y, A3.z, A3.w};
                    float c0 = bw0[kk], c1 = bw1[kk], c2 = bw2[kk], c3 = bw3[kk];
                    #pragma unroll
                    for (int i = 0; i < 16; i++) {
                        acc[i][0] += av[i] * c0;
                        acc[i][1] += av[i] * c1;
                        acc[i][2] += av[i] * c2;
                        acc[i][3] += av[i] * c3;
                    }
                }
            }
        }
    }
    float4 bb = *reinterpret_cast<const float4*>(bias + v0 + vi * 4);
    #pragma unroll
    for (int i = 0; i < 16; i++) {
        int m = mi * 16 + i;
        if (m < cnt) {
            long ro = (long)rs[m] * VOCAB + v0 + vi * 4;
            *reinterpret_cast<float4*>(out + ro) =
                make_float4(acc[i][0] + bb.x, acc[i][1] + bb.y,
                            acc[i][2] + bb.z, acc[i][3] + bb.w);
        }
    }
}

// ------------------- launch -------------------
extern "C" void kernel_launch(void* const* d_in, const int* in_sizes, int n_in,
                              void* d_out, int out_size) {
    const float* embed = (const float*)d_in[0];
    const float* Wpar  = (const float*)d_in[1];
    const float* bpar  = (const float*)d_in[2];
    const float* Wmu   = (const float*)d_in[3];
    const float* bmu   = (const float*)d_in[4];
    const float* Wlv   = (const float*)d_in[5];
    const float* blv   = (const float*)d_in[6];
    const float* W1    = (const float*)d_in[7];
    const float* b1    = (const float*)d_in[8];
    const float* W2    = (const float*)d_in[9];
    const float* b2    = (const float*)d_in[10];
    const float* Wl    = (const float*)d_in[11];
    const float* bl    = (const float*)d_in[12];
    const float* Wp    = (const float*)d_in[13];
    const float* bp    = (const float*)d_in[14];
    const float* eps   = (const float*)d_in[15];
    const int*   values= (const int*)d_in[16];
    float* out = (float*)d_out;

    cudaFuncSetAttribute(dec_cluster, cudaFuncAttributeMaxDynamicSharedMemorySize,
                         DEC_SMEM_BYTES);

    prep_w2t<<<64, 1024>>>(W2);
    prep_wpc<<<256, 256>>>(Wp, W2, b2, bp);
    for (int d = 7; d >= 0; d--) {
        int first = (1 << d) - 1;
        int count = 1 << d;
        int blocks = (count + 1) / 2;
        enc_level<<<blocks, 256>>>(embed, values, Wpar, bpar, first, count, d == 7 ? 1 : 0);
    }
    latent_k<<<1, 256>>>(Wmu, bmu, Wlv, blv, eps, out);
    dec_cluster<<<8, 256, DEC_SMEM_BYTES>>>(W1, b1, W2, b2);
    co1_k<<<MAX_STEPS, 256>>>(b2);
    zero_rows<<<MAX_STEPS, 256>>>(out);
    value_gemm<<<dim3(VOCAB / 128, 2), 256>>>(Wl, bl, Wp, bp, out);
}